// round 2
// baseline (speedup 1.0000x reference)
#include <cuda_runtime.h>
#include <math.h>

#define Bq   2
#define Tq   4096
#define Cq   768
#define Hq   12
#define HDq  64
#define Mq   (Bq*Tq)       // 8192 tokens
#define NQKV (3*Cq)        // 2304

// ---- scratch (device globals; no allocations allowed) ----
__device__ float g_q[(size_t)Bq*Hq*Tq*HDq];   // [B,H,T,hd]
__device__ float g_k[(size_t)Bq*Hq*Tq*HDq];
__device__ float g_v[(size_t)Bq*Hq*Tq*HDq];
__device__ float g_att[(size_t)Mq*Cq];        // [B*T, C] attention output (pre-proj)

// ============================================================================
// SGEMM: C[M,N] = A[M,K] @ W[K,N] + bias
//   EPI==1: A = Ain (x), epilogue scatters into g_q/g_k/g_v with [B,H,T,hd] layout
//   EPI==0: A = g_att,   epilogue writes out[M,N] with bias (final projection)
// BM=BN=128, BK=8, 256 threads, 8x8 micro-tile. M%128==0, N%128==0, K%8==0 hold.
// ============================================================================
template<int EPI>
__global__ __launch_bounds__(256)
void sgemm_kernel(const float* __restrict__ Ain, const float* __restrict__ W,
                  const float* __restrict__ bias, float* __restrict__ out,
                  int M, int N, int K)
{
    const float* A = (EPI == 0) ? g_att : Ain;

    __shared__ float As[8][128];
    __shared__ float Bs[8][128];

    const int tid     = threadIdx.x;
    const int rowBase = blockIdx.y * 128;
    const int colBase = blockIdx.x * 128;
    const int ty = tid >> 4, tx = tid & 15;

    const int arow = tid >> 1,  acol = (tid & 1) << 2;   // A: 128 rows x 8 k
    const int brow = tid >> 5,  bcol = (tid & 31) << 2;  // B: 8 k x 128 cols

    const float* Ap = A + (size_t)(rowBase + arow) * K + acol;
    const float* Wp = W + (size_t)brow * N + colBase + bcol;

    float acc[8][8];
    #pragma unroll
    for (int i = 0; i < 8; i++)
        #pragma unroll
        for (int j = 0; j < 8; j++) acc[i][j] = 0.f;

    for (int k0 = 0; k0 < K; k0 += 8) {
        float4 av = *(const float4*)(Ap + k0);
        float4 bv = *(const float4*)(Wp + (size_t)k0 * N);
        As[acol+0][arow] = av.x;
        As[acol+1][arow] = av.y;
        As[acol+2][arow] = av.z;
        As[acol+3][arow] = av.w;
        *(float4*)&Bs[brow][bcol] = bv;
        __syncthreads();

        #pragma unroll
        for (int kk = 0; kk < 8; kk++) {
            float a[8], bb[8];
            *(float4*)(a)     = *(const float4*)&As[kk][ty*8];
            *(float4*)(a + 4) = *(const float4*)&As[kk][ty*8 + 4];
            *(float4*)(bb)     = *(const float4*)&Bs[kk][tx*8];
            *(float4*)(bb + 4) = *(const float4*)&Bs[kk][tx*8 + 4];
            #pragma unroll
            for (int i = 0; i < 8; i++)
                #pragma unroll
                for (int j = 0; j < 8; j++)
                    acc[i][j] += a[i] * bb[j];
        }
        __syncthreads();
    }

    if (EPI == 1) {
        // scatter QKV: col c in [0,2304): part=c/768, head=(c%768)/64, d=c%64
        #pragma unroll
        for (int i = 0; i < 8; i++) {
            int gr = rowBase + ty*8 + i;          // token index
            int bb2 = gr >> 12;                   // / Tq (4096)
            int tt  = gr & (Tq - 1);
            #pragma unroll
            for (int j = 0; j < 8; j++) {
                int gc = colBase + tx*8 + j;
                float v = acc[i][j] + bias[gc];
                int part = gc / Cq;
                int rem  = gc - part * Cq;
                int hh = rem >> 6, dd = rem & 63;
                size_t dst = (((size_t)bb2 * Hq + hh) * Tq + tt) * HDq + dd;
                if      (part == 0) g_q[dst] = v;
                else if (part == 1) g_k[dst] = v;
                else                g_v[dst] = v;
            }
        }
    } else {
        #pragma unroll
        for (int i = 0; i < 8; i++) {
            size_t gr = rowBase + ty*8 + i;
            #pragma unroll
            for (int j = 0; j < 8; j += 4) {
                int gc = colBase + tx*8 + j;
                float4 v;
                v.x = acc[i][j+0] + bias[gc+0];
                v.y = acc[i][j+1] + bias[gc+1];
                v.z = acc[i][j+2] + bias[gc+2];
                v.w = acc[i][j+3] + bias[gc+3];
                *(float4*)&out[gr * N + gc] = v;
            }
        }
    }
}

// ============================================================================
// Flash attention (fp32, causal): 64x64 tiles, online softmax, only nt<=mt.
// 256 threads, each thread owns a 4x4 micro-tile (16x16 thread grid).
// SMEM row stride 65 -> conflict-free K-row column reads.
// Softmax scale (1/8) is folded into the Q tile at load time.
// ============================================================================
#define FS 65

__global__ __launch_bounds__(256)
void flash_kernel(const int* __restrict__ amask)
{
    extern __shared__ float sm[];
    float* Qs   = sm;                 // 64*FS
    float* Ks   = Qs + 64*FS;
    float* Vs   = Ks + 64*FS;
    float* Ss   = Vs + 64*FS;         // holds P tile
    float* red  = Ss + 64*FS;         // 64*16 partial reduce
    float* m_s  = red + 64*16;        // 64
    float* l_s  = m_s + 64;           // 64
    float* al_s = l_s + 64;           // 64
    float* pad_s= al_s + 64;          // 64

    const int tid = threadIdx.x;
    const int mt  = blockIdx.x;
    const int bh  = blockIdx.y;
    const int b = bh / Hq, h = bh % Hq;
    const int row0 = mt * 64;

    const size_t base = ((size_t)(b * Hq + h)) * Tq * HDq;
    const float* Qg = g_q + base;
    const float* Kg = g_k + base;
    const float* Vg = g_v + base;

    // load Q tile, pre-scaled by 1/sqrt(hd)
    const float scale = 0.125f;
    for (int idx = tid; idx < 64*64; idx += 256) {
        int r = idx >> 6, c = idx & 63;
        Qs[r*FS + c] = Qg[(size_t)(row0 + r)*HDq + c] * scale;
    }
    if (tid < 64) { m_s[tid] = -1e30f; l_s[tid] = 0.f; }

    const int ty = tid >> 4, tx = tid & 15;
    const int r0 = ty*4, c0 = tx*4;
    float acc[4][4];
    #pragma unroll
    for (int i = 0; i < 4; i++)
        #pragma unroll
        for (int j = 0; j < 4; j++) acc[i][j] = 0.f;
    __syncthreads();

    for (int nt = 0; nt <= mt; nt++) {
        const int col0 = nt * 64;
        for (int idx = tid; idx < 64*64; idx += 256) {
            int r = idx >> 6, c = idx & 63;
            Ks[r*FS + c] = Kg[(size_t)(col0 + r)*HDq + c];
            Vs[r*FS + c] = Vg[(size_t)(col0 + r)*HDq + c];
        }
        if (tid < 64)
            pad_s[tid] = (1.0f - (float)amask[b*Tq + col0 + tid]) * -1e9f;
        __syncthreads();

        // S = (Q*scale) @ K^T + masks
        float s[4][4];
        #pragma unroll
        for (int i = 0; i < 4; i++)
            #pragma unroll
            for (int j = 0; j < 4; j++) s[i][j] = 0.f;

        #pragma unroll 4
        for (int d = 0; d < 64; d++) {
            float q[4], kv[4];
            #pragma unroll
            for (int i = 0; i < 4; i++) q[i]  = Qs[(r0+i)*FS + d];
            #pragma unroll
            for (int j = 0; j < 4; j++) kv[j] = Ks[(c0+j)*FS + d];
            #pragma unroll
            for (int i = 0; i < 4; i++)
                #pragma unroll
                for (int j = 0; j < 4; j++)
                    s[i][j] += q[i] * kv[j];
        }
        #pragma unroll
        for (int i = 0; i < 4; i++)
            #pragma unroll
            for (int j = 0; j < 4; j++) {
                float v = s[i][j] + pad_s[c0+j];
                if (nt == mt && (col0 + c0 + j) > (row0 + r0 + i)) v -= 10000.0f;
                s[i][j] = v;
            }

        // per-thread row-max partials
        #pragma unroll
        for (int i = 0; i < 4; i++) {
            float mx = fmaxf(fmaxf(s[i][0], s[i][1]), fmaxf(s[i][2], s[i][3]));
            red[(r0+i)*16 + tx] = mx;
        }
        __syncthreads();
        if (tid < 64) {
            float mo = m_s[tid], mn = mo;
            #pragma unroll
            for (int t = 0; t < 16; t++) mn = fmaxf(mn, red[tid*16 + t]);
            float a = __expf(mo - mn);
            m_s[tid] = mn; al_s[tid] = a; l_s[tid] *= a;
        }
        __syncthreads();

        // P = exp(S - m), rescale acc, partial row sums
        #pragma unroll
        for (int i = 0; i < 4; i++) {
            float mn = m_s[r0+i];
            float a  = al_s[r0+i];
            float rs = 0.f;
            #pragma unroll
            for (int j = 0; j < 4; j++) {
                float p = __expf(s[i][j] - mn);
                Ss[(r0+i)*FS + (c0+j)] = p;
                rs += p;
                acc[i][j] *= a;
            }
            red[(r0+i)*16 + tx] = rs;
        }
        __syncthreads();
        if (tid < 64) {
            float sum = 0.f;
            #pragma unroll
            for (int t = 0; t < 16; t++) sum += red[tid*16 + t];
            l_s[tid] += sum;
        }

        // O += P @ V
        #pragma unroll 4
        for (int k = 0; k < 64; k++) {
            float p[4], vv[4];
            #pragma unroll
            for (int i = 0; i < 4; i++) p[i]  = Ss[(r0+i)*FS + k];
            #pragma unroll
            for (int j = 0; j < 4; j++) vv[j] = Vs[k*FS + c0 + j];
            #pragma unroll
            for (int i = 0; i < 4; i++)
                #pragma unroll
                for (int j = 0; j < 4; j++)
                    acc[i][j] += p[i] * vv[j];
        }
        __syncthreads();
    }

    // epilogue: normalize, write [B,T,C] with head interleave undone
    #pragma unroll
    for (int i = 0; i < 4; i++) {
        float inv = 1.0f / l_s[r0+i];
        int t = row0 + r0 + i;
        #pragma unroll
        for (int j = 0; j < 4; j++)
            g_att[((size_t)(b*Tq + t)) * Cq + h*HDq + c0 + j] = acc[i][j] * inv;
    }
}

// ============================================================================
extern "C" void kernel_launch(void* const* d_in, const int* in_sizes, int n_in,
                              void* d_out, int out_size)
{
    const float* x      = (const float*)d_in[0];
    const int*   amask  = (const int*)  d_in[1];
    const float* W_attn = (const float*)d_in[2];
    const float* b_attn = (const float*)d_in[3];
    const float* W_proj = (const float*)d_in[4];
    const float* b_proj = (const float*)d_in[5];
    float* out = (float*)d_out;

    dim3 blk(256);

    // 1) QKV = x @ W_attn + b_attn, scattered into [B,H,T,hd] Q/K/V
    sgemm_kernel<1><<<dim3(NQKV/128, Mq/128), blk>>>(x, W_attn, b_attn, nullptr,
                                                     Mq, NQKV, Cq);

    // 2) flash attention (causal) -> g_att [B*T, C]
    size_t smem = (size_t)(4*64*FS + 64*16 + 4*64) * sizeof(float);
    cudaFuncSetAttribute(flash_kernel,
                         cudaFuncAttributeMaxDynamicSharedMemorySize, (int)smem);
    flash_kernel<<<dim3(Tq/64, Bq*Hq), blk, smem>>>(amask);

    // 3) out = g_att @ W_proj + b_proj
    sgemm_kernel<0><<<dim3(Cq/128, Mq/128), blk>>>(nullptr, W_proj, b_proj, out,
                                                   Mq, Cq, Cq);
}

// round 9
// speedup vs baseline: 2.2685x; 2.2685x over previous
#include <cuda_runtime.h>
#include <math.h>
#include <stdint.h>

#define Bq   2
#define Tq   4096
#define Cq   768
#define Hq   12
#define HDq  64
#define Mq   (Bq*Tq)       // 8192 tokens
#define NQKV (3*Cq)        // 2304

// ---- scratch (device globals; no allocations allowed) ----
__device__ float g_q[(size_t)Bq*Hq*Tq*HDq];   // [B,H,T,hd]
__device__ float g_k[(size_t)Bq*Hq*Tq*HDq];
__device__ float g_v[(size_t)Bq*Hq*Tq*HDq];
__device__ float g_att[(size_t)Mq*Cq];        // [B*T, C] attention output (pre-proj)

// ---- tf32 helpers ----
__device__ __forceinline__ float tf32r(float x) {
    float y;
    asm("cvt.rna.tf32.f32 %0, %1;" : "=f"(y) : "f"(x));
    return y;
}

// D += A(16x8) * B(8x8), tf32 inputs, f32 accum
__device__ __forceinline__ void mma_tf32(float* d, const uint32_t* a,
                                         uint32_t b0, uint32_t b1) {
    asm volatile(
        "mma.sync.aligned.m16n8k8.row.col.f32.tf32.tf32.f32 "
        "{%0,%1,%2,%3}, {%4,%5,%6,%7}, {%8,%9}, {%0,%1,%2,%3};\n"
        : "+f"(d[0]), "+f"(d[1]), "+f"(d[2]), "+f"(d[3])
        : "r"(a[0]), "r"(a[1]), "r"(a[2]), "r"(a[3]), "r"(b0), "r"(b1));
}

// ============================================================================
// tf32 tensor-core GEMM: C[M,N] = A[M,K] @ W[K,N] + bias
//   EPI==1: A = Ain (x), epilogue scatters into g_q/g_k/g_v ([B,H,T,hd])
//   EPI==0: A = g_att,   epilogue writes out[M,N] + bias
// BM=128, BN=128, BK=32, 256 threads = 8 warps, warp tile 32m x 64n.
// ============================================================================
#define PA 36    // As row pad: frag addr bank = 4g+t -> 32 distinct banks
#define PB 136   // Bs row pad: frag addr bank = 8t+g -> 32 distinct banks

template<int EPI>
__global__ __launch_bounds__(256)
void sgemm_tc(const float* __restrict__ Ain, const float* __restrict__ W,
              const float* __restrict__ bias, float* __restrict__ out,
              int M, int N, int K)
{
    const float* A = (EPI == 0) ? g_att : Ain;

    __shared__ float As[128 * PA];   // [row][k] 128x32
    __shared__ float Bs[32 * PB];    // [k][n]   32x128

    const int tid  = threadIdx.x;
    const int w    = tid >> 5;
    const int lane = tid & 31;
    const int g    = lane >> 2;     // groupID
    const int t    = lane & 3;      // thread-in-group
    const int wm   = w >> 1;        // 0..3  (m: 4 x 32)
    const int wn   = w & 1;         // 0..1  (n: 2 x 64)

    const int rowBase = blockIdx.y * 128;
    const int colBase = blockIdx.x * 128;

    float acc[2][8][4];
    #pragma unroll
    for (int mi = 0; mi < 2; mi++)
        #pragma unroll
        for (int j = 0; j < 8; j++)
            #pragma unroll
            for (int c = 0; c < 4; c++) acc[mi][j][c] = 0.f;

    for (int k0 = 0; k0 < K; k0 += 32) {
        // load A tile 128x32 (f4 per thread x4), cvt to tf32
        #pragma unroll
        for (int i = 0; i < 4; i++) {
            int idx = tid + i * 256;
            int r = idx >> 3, cq = (idx & 7) * 4;
            float4 v = *(const float4*)(A + (size_t)(rowBase + r) * K + k0 + cq);
            As[r * PA + cq + 0] = tf32r(v.x);
            As[r * PA + cq + 1] = tf32r(v.y);
            As[r * PA + cq + 2] = tf32r(v.z);
            As[r * PA + cq + 3] = tf32r(v.w);
        }
        // load B tile 32x128
        #pragma unroll
        for (int i = 0; i < 4; i++) {
            int idx = tid + i * 256;
            int r = idx >> 5, cq = (idx & 31) * 4;
            float4 v = *(const float4*)(W + (size_t)(k0 + r) * N + colBase + cq);
            Bs[r * PB + cq + 0] = tf32r(v.x);
            Bs[r * PB + cq + 1] = tf32r(v.y);
            Bs[r * PB + cq + 2] = tf32r(v.z);
            Bs[r * PB + cq + 3] = tf32r(v.w);
        }
        __syncthreads();

        #pragma unroll
        for (int ks = 0; ks < 4; ks++) {
            int k = ks * 8;
            uint32_t af[2][4];
            #pragma unroll
            for (int mi = 0; mi < 2; mi++) {
                int r = wm * 32 + mi * 16;
                af[mi][0] = __float_as_uint(As[(r + g    ) * PA + k + t    ]);
                af[mi][1] = __float_as_uint(As[(r + g + 8) * PA + k + t    ]);
                af[mi][2] = __float_as_uint(As[(r + g    ) * PA + k + t + 4]);
                af[mi][3] = __float_as_uint(As[(r + g + 8) * PA + k + t + 4]);
            }
            #pragma unroll
            for (int j = 0; j < 8; j++) {
                int n = wn * 64 + j * 8;
                uint32_t b0 = __float_as_uint(Bs[(k + t    ) * PB + n + g]);
                uint32_t b1 = __float_as_uint(Bs[(k + t + 4) * PB + n + g]);
                mma_tf32(acc[0][j], af[0], b0, b1);
                mma_tf32(acc[1][j], af[1], b0, b1);
            }
        }
        __syncthreads();
    }

    // epilogue
    #pragma unroll
    for (int mi = 0; mi < 2; mi++) {
        #pragma unroll
        for (int ci = 0; ci < 2; ci++) {           // ci=0 -> rows g, ci=1 -> rows g+8
            int row = rowBase + wm * 32 + mi * 16 + g + ci * 8;
            #pragma unroll
            for (int j = 0; j < 8; j++) {
                int col = colBase + wn * 64 + j * 8 + 2 * t;
                float v0 = acc[mi][j][ci * 2 + 0] + bias[col];
                float v1 = acc[mi][j][ci * 2 + 1] + bias[col + 1];
                if (EPI == 1) {
                    int bb = row >> 12;            // / Tq
                    int tt = row & (Tq - 1);
                    #pragma unroll
                    for (int e = 0; e < 2; e++) {
                        int gc = col + e;
                        float v = e ? v1 : v0;
                        int part = gc / Cq;
                        int rem  = gc - part * Cq;
                        int hh = rem >> 6, dd = rem & 63;
                        size_t dst = (((size_t)bb * Hq + hh) * Tq + tt) * HDq + dd;
                        if      (part == 0) g_q[dst] = v;
                        else if (part == 1) g_k[dst] = v;
                        else                g_v[dst] = v;
                    }
                } else {
                    float2 v2 = make_float2(v0, v1);
                    *(float2*)&out[(size_t)row * N + col] = v2;
                }
            }
        }
    }
}

// ============================================================================
// Flash attention, tf32 tensor cores, causal.
// Q tile 128 rows x 64, K/V tiles 64 x 64. 8 warps; warp w owns rows
// [16w,16w+16) -> softmax is fully warp-local (shfl over tig quad).
// Q fragments persist in registers across the whole kernel.
// ============================================================================
#define PK 68    // Ks/Ps pad: A/B-frag addr bank = 4g+t / 4g+t -> conflict-free
#define PV 72    // Vs pad:    B-frag addr bank = 8t+g -> conflict-free

__global__ __launch_bounds__(256)
void flash_tc(const int* __restrict__ amask)
{
    extern __shared__ float sm[];
    float* Ks    = sm;                    // 64*PK
    float* Vs    = Ks + 64 * PK;          // 64*PV
    float* Ps    = Vs + 64 * PV;          // 128*PK (also Q staging)
    float* pad_s = Ps + 128 * PK;         // 64

    const int tid  = threadIdx.x;
    const int w    = tid >> 5;
    const int lane = tid & 31;
    const int g    = lane >> 2;
    const int t    = lane & 3;
    const int wrow = w * 16;

    const int mt = blockIdx.x;            // 32 tiles of 128 rows
    const int bh = blockIdx.y;
    const int b = bh / Hq, h = bh % Hq;
    const int row0 = mt * 128;

    const size_t base = ((size_t)(b * Hq + h)) * Tq * HDq;
    const float* Qg = g_q + base;
    const float* Kg = g_k + base;
    const float* Vg = g_v + base;

    // ---- stage Q (pre-scaled, tf32) via Ps, then load persistent Q frags ----
    for (int idx = tid; idx < 128 * 64; idx += 256) {
        int r = idx >> 6, c = idx & 63;
        Ps[r * PK + c] = tf32r(Qg[(size_t)(row0 + r) * HDq + c] * 0.125f);
    }
    __syncthreads();
    uint32_t qf[8][4];
    #pragma unroll
    for (int ks = 0; ks < 8; ks++) {
        int k = ks * 8;
        qf[ks][0] = __float_as_uint(Ps[(wrow + g    ) * PK + k + t    ]);
        qf[ks][1] = __float_as_uint(Ps[(wrow + g + 8) * PK + k + t    ]);
        qf[ks][2] = __float_as_uint(Ps[(wrow + g    ) * PK + k + t + 4]);
        qf[ks][3] = __float_as_uint(Ps[(wrow + g + 8) * PK + k + t + 4]);
    }

    float o[8][4];
    #pragma unroll
    for (int j = 0; j < 8; j++)
        #pragma unroll
        for (int c = 0; c < 4; c++) o[j][c] = 0.f;
    float m_lo = -1e30f, m_hi = -1e30f, l_lo = 0.f, l_hi = 0.f;

    const int rlo = row0 + wrow + g;
    const int rhi = rlo + 8;
    const int ntmax = 2 * mt + 1;

    for (int nt = 0; nt <= ntmax; nt++) {
        const int col0 = nt * 64;
        __syncthreads();   // previous iter's MMAs done with Ks/Vs
        for (int idx = tid; idx < 64 * 64; idx += 256) {
            int r = idx >> 6, c = idx & 63;
            Ks[r * PK + c] = tf32r(Kg[(size_t)(col0 + r) * HDq + c]);
            Vs[r * PV + c] = tf32r(Vg[(size_t)(col0 + r) * HDq + c]);
        }
        if (tid < 64)
            pad_s[tid] = (1.0f - (float)amask[b * Tq + col0 + tid]) * -1e9f;
        __syncthreads();

        // ---- S = Q @ K^T ----
        float sacc[8][4];
        #pragma unroll
        for (int j = 0; j < 8; j++)
            #pragma unroll
            for (int c = 0; c < 4; c++) sacc[j][c] = 0.f;

        #pragma unroll
        for (int ks = 0; ks < 8; ks++) {
            int k = ks * 8;
            #pragma unroll
            for (int j = 0; j < 8; j++) {
                uint32_t b0 = __float_as_uint(Ks[(j * 8 + g) * PK + k + t    ]);
                uint32_t b1 = __float_as_uint(Ks[(j * 8 + g) * PK + k + t + 4]);
                mma_tf32(sacc[j], qf[ks], b0, b1);
            }
        }

        // ---- mask + warp-local online softmax ----
        float mlo = -1e30f, mhi = -1e30f;
        #pragma unroll
        for (int j = 0; j < 8; j++) {
            int c0g = col0 + j * 8 + 2 * t;
            float p0 = pad_s[j * 8 + 2 * t], p1 = pad_s[j * 8 + 2 * t + 1];
            float v0 = sacc[j][0] + p0 + ((c0g     > rlo) ? -10000.f : 0.f);
            float v1 = sacc[j][1] + p1 + ((c0g + 1 > rlo) ? -10000.f : 0.f);
            float v2 = sacc[j][2] + p0 + ((c0g     > rhi) ? -10000.f : 0.f);
            float v3 = sacc[j][3] + p1 + ((c0g + 1 > rhi) ? -10000.f : 0.f);
            sacc[j][0] = v0; sacc[j][1] = v1; sacc[j][2] = v2; sacc[j][3] = v3;
            mlo = fmaxf(mlo, fmaxf(v0, v1));
            mhi = fmaxf(mhi, fmaxf(v2, v3));
        }
        mlo = fmaxf(mlo, __shfl_xor_sync(0xffffffffu, mlo, 1));
        mlo = fmaxf(mlo, __shfl_xor_sync(0xffffffffu, mlo, 2));
        mhi = fmaxf(mhi, __shfl_xor_sync(0xffffffffu, mhi, 1));
        mhi = fmaxf(mhi, __shfl_xor_sync(0xffffffffu, mhi, 2));

        float mnl = fmaxf(m_lo, mlo), mnh = fmaxf(m_hi, mhi);
        float al = __expf(m_lo - mnl), ah = __expf(m_hi - mnh);
        m_lo = mnl; m_hi = mnh;

        float sl = 0.f, sh = 0.f;
        #pragma unroll
        for (int j = 0; j < 8; j++) {
            float p0 = __expf(sacc[j][0] - mnl);
            float p1 = __expf(sacc[j][1] - mnl);
            float p2 = __expf(sacc[j][2] - mnh);
            float p3 = __expf(sacc[j][3] - mnh);
            int cc = j * 8 + 2 * t;
            Ps[(wrow + g    ) * PK + cc    ] = tf32r(p0);
            Ps[(wrow + g    ) * PK + cc + 1] = tf32r(p1);
            Ps[(wrow + g + 8) * PK + cc    ] = tf32r(p2);
            Ps[(wrow + g + 8) * PK + cc + 1] = tf32r(p3);
            sl += p0 + p1;  sh += p2 + p3;
            o[j][0] *= al; o[j][1] *= al; o[j][2] *= ah; o[j][3] *= ah;
        }
        sl += __shfl_xor_sync(0xffffffffu, sl, 1);
        sl += __shfl_xor_sync(0xffffffffu, sl, 2);
        sh += __shfl_xor_sync(0xffffffffu, sh, 1);
        sh += __shfl_xor_sync(0xffffffffu, sh, 2);
        l_lo = l_lo * al + sl;
        l_hi = l_hi * ah + sh;
        __syncwarp();

        // ---- O += P @ V ----
        #pragma unroll
        for (int ks = 0; ks < 8; ks++) {
            int k = ks * 8;
            uint32_t af[4];
            af[0] = __float_as_uint(Ps[(wrow + g    ) * PK + k + t    ]);
            af[1] = __float_as_uint(Ps[(wrow + g + 8) * PK + k + t    ]);
            af[2] = __float_as_uint(Ps[(wrow + g    ) * PK + k + t + 4]);
            af[3] = __float_as_uint(Ps[(wrow + g + 8) * PK + k + t + 4]);
            #pragma unroll
            for (int j = 0; j < 8; j++) {
                uint32_t b0 = __float_as_uint(Vs[(k + t    ) * PV + j * 8 + g]);
                uint32_t b1 = __float_as_uint(Vs[(k + t + 4) * PV + j * 8 + g]);
                mma_tf32(o[j], af, b0, b1);
            }
        }
    }

    // ---- epilogue: normalize, write [B,T,C] ----
    float il = 1.f / l_lo, ih = 1.f / l_hi;
    int tlo = row0 + wrow + g, thi = tlo + 8;
    #pragma unroll
    for (int j = 0; j < 8; j++) {
        int c = h * HDq + j * 8 + 2 * t;
        float2 vlo = make_float2(o[j][0] * il, o[j][1] * il);
        float2 vhi = make_float2(o[j][2] * ih, o[j][3] * ih);
        *(float2*)&g_att[((size_t)(b * Tq + tlo)) * Cq + c] = vlo;
        *(float2*)&g_att[((size_t)(b * Tq + thi)) * Cq + c] = vhi;
    }
}

// ============================================================================
extern "C" void kernel_launch(void* const* d_in, const int* in_sizes, int n_in,
                              void* d_out, int out_size)
{
    const float* x      = (const float*)d_in[0];
    const int*   amask  = (const int*)  d_in[1];
    const float* W_attn = (const float*)d_in[2];
    const float* b_attn = (const float*)d_in[3];
    const float* W_proj = (const float*)d_in[4];
    const float* b_proj = (const float*)d_in[5];
    float* out = (float*)d_out;

    dim3 blk(256);

    // 1) QKV = x @ W_attn + b_attn -> scattered Q/K/V [B,H,T,hd]
    sgemm_tc<1><<<dim3(NQKV/128, Mq/128), blk>>>(x, W_attn, b_attn, nullptr,
                                                 Mq, NQKV, Cq);

    // 2) flash attention (causal, tf32 MMA) -> g_att [B*T, C]
    size_t smem = (size_t)(64*PK + 64*PV + 128*PK + 64) * sizeof(float);
    cudaFuncSetAttribute(flash_tc,
                         cudaFuncAttributeMaxDynamicSharedMemorySize, (int)smem);
    flash_tc<<<dim3(Tq/128, Bq*Hq), blk, smem>>>(amask);

    // 3) out = g_att @ W_proj + b_proj
    sgemm_tc<0><<<dim3(Cq/128, Mq/128), blk>>>(nullptr, W_proj, b_proj, out,
                                               Mq, Cq, Cq);
}